// round 1
// baseline (speedup 1.0000x reference)
#include <cuda_runtime.h>
#include <cuda_bf16.h>
#include <cstdint>

// Problem constants (fixed by the reference generator).
#define HH 512
#define WW 1024
#define CC 16      // BG_RANK
#define FC 128     // FEATC

// Transposed bf16 background: bgT[y][x][c], 16 bf16 = 32B per texel = 2 uint4.
// 512*1024*2 uint4 = 16 MB static device scratch (allocation-free rule).
__device__ uint4 g_bgT[HH * WW * 2];

// ---------------------------------------------------------------------------
// Kernel 1: transpose bg_mat [16][512][1024] fp32  ->  g_bgT [512*1024][16] bf16
// Reads coalesced per-channel (warp reads 128B lines), writes 32B/thread.
// ---------------------------------------------------------------------------
__global__ void transpose_bg(const float* __restrict__ bg) {
    int idx = blockIdx.x * blockDim.x + threadIdx.x;   // y*WW + x
    if (idx >= HH * WW) return;
    uint32_t p[8];
#pragma unroll
    for (int c = 0; c < 8; c++) {
        float a = bg[(2 * c)     * (HH * WW) + idx];
        float b = bg[(2 * c + 1) * (HH * WW) + idx];
        __nv_bfloat162 h = __floats2bfloat162_rn(a, b);  // lo = ch 2c, hi = ch 2c+1
        p[c] = *reinterpret_cast<uint32_t*>(&h);
    }
    g_bgT[idx * 2 + 0] = make_uint4(p[0], p[1], p[2], p[3]);
    g_bgT[idx * 2 + 1] = make_uint4(p[4], p[5], p[6], p[7]);
}

// ---------------------------------------------------------------------------
// Kernel 2: per-warp pipeline over 32 rays:
//   unwrap -> bilinear gather (bf16 texels, fp32 blend) -> stage A tile (bf16)
//   -> ldmatrix -> 2x16 mma.sync m16n8k16 (bf16 in, fp32 acc)  [h = emb @ W1]
//   -> fused ReLU + W2 contraction in fp32 regs -> quad shuffle-reduce
//   -> softplus -> store 3 floats/ray.
// W1 lives in registers as persistent B-fragments (32 regs/thread).
// ---------------------------------------------------------------------------
__global__ void __launch_bounds__(256)
render_kernel(const float* __restrict__ viewdirs,
              const float* __restrict__ W1,
              const float* __restrict__ W2,
              float* __restrict__ out,
              int nRays)
{
    __shared__ float W2s[FC * 4];                       // [j][4], .w padding unused
    __shared__ __align__(16) uint32_t Astage[8 * 32 * 12];  // per warp: 32 rows * 48B

    const int tid  = threadIdx.x;
    const int lane = tid & 31;
    const int warp = tid >> 5;
    const int g    = lane >> 2;   // group id 0..7 (row within m16 half / B col)
    const int tg   = lane & 3;    // thread-in-group 0..3 (k pair / acc col pair)

    // Stage W2 [128][3] -> padded [128][4] in smem.
    for (int i = tid; i < FC * 3; i += blockDim.x)
        W2s[(i / 3) * 4 + (i % 3)] = W2[i];
    __syncthreads();

    // Persistent B fragments for W1 (16 n-chunks of 8 cols, k=16).
    // b0 halves: (W1[k0][col], W1[k0+1][col]); b1: k0+8.  col = 8t + g, k0 = 2*tg.
    uint32_t bw0[16], bw1[16];
#pragma unroll
    for (int t = 0; t < 16; t++) {
        int col = t * 8 + g;
        int k0  = tg * 2;
        __nv_bfloat162 p0 = __floats2bfloat162_rn(W1[(k0    ) * FC + col],
                                                  W1[(k0 + 1) * FC + col]);
        __nv_bfloat162 p1 = __floats2bfloat162_rn(W1[(k0 + 8) * FC + col],
                                                  W1[(k0 + 9) * FC + col]);
        bw0[t] = *reinterpret_cast<uint32_t*>(&p0);
        bw1[t] = *reinterpret_cast<uint32_t*>(&p1);
    }

    const int rayBase = blockIdx.x * 256 + warp * 32;
    const int ray     = rayBase + lane;

    // ---- unwrap + bilinear gather (fp32 blend of bf16 texels) ----
    float emb[16];
#pragma unroll
    for (int c = 0; c < 16; c++) emb[c] = 0.f;

    if (ray < nRays) {
        float dx = viewdirs[3 * ray + 0];
        float dy = viewdirs[3 * ray + 1];
        float dz = viewdirs[3 * ray + 2];
        const float INV_PI = 0.318309886183790671538f;
        float phi   = atan2f(dy, dx);
        float theta = acosf(fminf(fmaxf(dz, -1.f), 1.f));
        float gx = phi * INV_PI;
        float gy = theta * (2.f * INV_PI) - 1.f;
        float ix = (gx + 1.f) * (0.5f * WW) - 0.5f;
        float iy = (gy + 1.f) * (0.5f * HH) - 0.5f;
        float x0 = floorf(ix), y0 = floorf(iy);
        float fx = ix - x0,    fy = iy - y0;
        float wx[2] = {1.f - fx, fx};
        float wy[2] = {1.f - fy, fy};
#pragma unroll
        for (int cy = 0; cy < 2; cy++) {
#pragma unroll
            for (int cx = 0; cx < 2; cx++) {
                float xf = x0 + (float)cx;
                float yf = y0 + (float)cy;
                bool valid = (xf >= 0.f) & (xf <= (float)(WW - 1)) &
                             (yf >= 0.f) & (yf <= (float)(HH - 1));
                float w = wx[cx] * wy[cy] * (valid ? 1.f : 0.f);
                int xi = (int)fminf(fmaxf(xf, 0.f), (float)(WW - 1));
                int yi = (int)fminf(fmaxf(yf, 0.f), (float)(HH - 1));
                const uint4* p = &g_bgT[(yi * WW + xi) * 2];
                uint4 v0 = p[0];
                uint4 v1 = p[1];
                uint32_t u[8] = {v0.x, v0.y, v0.z, v0.w, v1.x, v1.y, v1.z, v1.w};
#pragma unroll
                for (int j = 0; j < 8; j++) {
                    float lo = __uint_as_float(u[j] << 16);          // ch 2j
                    float hi = __uint_as_float(u[j] & 0xffff0000u);  // ch 2j+1
                    emb[2 * j + 0] = fmaf(w, lo, emb[2 * j + 0]);
                    emb[2 * j + 1] = fmaf(w, hi, emb[2 * j + 1]);
                }
            }
        }
    }

    // ---- stage A row (16 bf16 = 32B) at 48B stride (conflict-free ldmatrix) ----
    {
        uint32_t pk[8];
#pragma unroll
        for (int j = 0; j < 8; j++) {
            __nv_bfloat162 h = __floats2bfloat162_rn(emb[2 * j], emb[2 * j + 1]);
            pk[j] = *reinterpret_cast<uint32_t*>(&h);
        }
        uint4* arow = reinterpret_cast<uint4*>(&Astage[warp * 384 + lane * 12]);
        arow[0] = make_uint4(pk[0], pk[1], pk[2], pk[3]);
        arow[1] = make_uint4(pk[4], pk[5], pk[6], pk[7]);
    }
    __syncwarp();

    // ---- ldmatrix x4: tile0 = rays 0..15, tile1 = rays 16..31 ----
    uint32_t a0[4], a1[4];
    {
        int m = lane >> 3;                 // matrix id 0..3
        int r = lane & 7;
        int row    = (m & 1) * 8 + r;      // m0,m2: rows 0-7 ; m1,m3: rows 8-15
        int coloff = (m >> 1) * 16;        // m2,m3: k 8-15 (byte offset 16)
        uint32_t base  = (uint32_t)__cvta_generic_to_shared(&Astage[warp * 384]);
        uint32_t addr0 = base + row * 48 + coloff;
        uint32_t addr1 = addr0 + 16 * 48;
        asm volatile("ldmatrix.sync.aligned.m8n8.x4.shared.b16 {%0,%1,%2,%3}, [%4];"
                     : "=r"(a0[0]), "=r"(a0[1]), "=r"(a0[2]), "=r"(a0[3]) : "r"(addr0));
        asm volatile("ldmatrix.sync.aligned.m8n8.x4.shared.b16 {%0,%1,%2,%3}, [%4];"
                     : "=r"(a1[0]), "=r"(a1[1]), "=r"(a1[2]), "=r"(a1[3]) : "r"(addr1));
    }

    // ---- 16 n-chunks: mma (h = emb@W1) fused with ReLU + W2 contraction ----
    // Thread's acc rows: tile0 -> {g, g+8}, tile1 -> {g+16, g+24}; cols j0, j0+1.
    float xr[12];
#pragma unroll
    for (int i = 0; i < 12; i++) xr[i] = 0.f;

#pragma unroll
    for (int t = 0; t < 16; t++) {
        float d0 = 0.f, d1 = 0.f, d2 = 0.f, d3 = 0.f;
        float e0 = 0.f, e1 = 0.f, e2 = 0.f, e3 = 0.f;
        asm volatile(
            "mma.sync.aligned.m16n8k16.row.col.f32.bf16.bf16.f32 "
            "{%0,%1,%2,%3},{%4,%5,%6,%7},{%8,%9},{%0,%1,%2,%3};"
            : "+f"(d0), "+f"(d1), "+f"(d2), "+f"(d3)
            : "r"(a0[0]), "r"(a0[1]), "r"(a0[2]), "r"(a0[3]),
              "r"(bw0[t]), "r"(bw1[t]));
        asm volatile(
            "mma.sync.aligned.m16n8k16.row.col.f32.bf16.bf16.f32 "
            "{%0,%1,%2,%3},{%4,%5,%6,%7},{%8,%9},{%0,%1,%2,%3};"
            : "+f"(e0), "+f"(e1), "+f"(e2), "+f"(e3)
            : "r"(a1[0]), "r"(a1[1]), "r"(a1[2]), "r"(a1[3]),
              "r"(bw0[t]), "r"(bw1[t]));

        int j0 = t * 8 + tg * 2;
        float4 wA = *reinterpret_cast<const float4*>(&W2s[j0 * 4]);
        float4 wB = *reinterpret_cast<const float4*>(&W2s[j0 * 4 + 4]);
        float h;
        h = fmaxf(d0, 0.f); xr[0] = fmaf(h, wA.x, xr[0]); xr[1]  = fmaf(h, wA.y, xr[1]);  xr[2]  = fmaf(h, wA.z, xr[2]);
        h = fmaxf(d1, 0.f); xr[0] = fmaf(h, wB.x, xr[0]); xr[1]  = fmaf(h, wB.y, xr[1]);  xr[2]  = fmaf(h, wB.z, xr[2]);
        h = fmaxf(d2, 0.f); xr[3] = fmaf(h, wA.x, xr[3]); xr[4]  = fmaf(h, wA.y, xr[4]);  xr[5]  = fmaf(h, wA.z, xr[5]);
        h = fmaxf(d3, 0.f); xr[3] = fmaf(h, wB.x, xr[3]); xr[4]  = fmaf(h, wB.y, xr[4]);  xr[5]  = fmaf(h, wB.z, xr[5]);
        h = fmaxf(e0, 0.f); xr[6] = fmaf(h, wA.x, xr[6]); xr[7]  = fmaf(h, wA.y, xr[7]);  xr[8]  = fmaf(h, wA.z, xr[8]);
        h = fmaxf(e1, 0.f); xr[6] = fmaf(h, wB.x, xr[6]); xr[7]  = fmaf(h, wB.y, xr[7]);  xr[8]  = fmaf(h, wB.z, xr[8]);
        h = fmaxf(e2, 0.f); xr[9] = fmaf(h, wA.x, xr[9]); xr[10] = fmaf(h, wA.y, xr[10]); xr[11] = fmaf(h, wA.z, xr[11]);
        h = fmaxf(e3, 0.f); xr[9] = fmaf(h, wB.x, xr[9]); xr[10] = fmaf(h, wB.y, xr[10]); xr[11] = fmaf(h, wB.z, xr[11]);
    }

    // ---- reduce the 4-lane quad partials (cols are split across tg=0..3) ----
#pragma unroll
    for (int i = 0; i < 12; i++) {
        float v = xr[i];
        v += __shfl_xor_sync(0xffffffffu, v, 1);
        v += __shfl_xor_sync(0xffffffffu, v, 2);
        xr[i] = v;
    }

    // ---- softplus + store (quad leader owns rows g, g+8, g+16, g+24) ----
    if (tg == 0) {
        int rows[4] = {g, g + 8, g + 16, g + 24};
#pragma unroll
        for (int r = 0; r < 4; r++) {
            int rr = rayBase + rows[r];
            if (rr < nRays) {
#pragma unroll
                for (int k = 0; k < 3; k++) {
                    float x  = xr[r * 3 + k];
                    float sp = fmaxf(x, 0.f) + log1pf(expf(-fabsf(x)));
                    out[rr * 3 + k] = sp;
                }
            }
        }
    }
}

// ---------------------------------------------------------------------------
// Launch: transpose pre-pass, then the fused render kernel. Graph-capturable,
// allocation-free. Inputs (metadata order): viewdirs, roughness(unused),
// bg_mat, W1, W2.
// ---------------------------------------------------------------------------
extern "C" void kernel_launch(void* const* d_in, const int* in_sizes, int n_in,
                              void* d_out, int out_size) {
    const float* viewdirs = (const float*)d_in[0];
    const float* bg       = (const float*)d_in[2];
    const float* W1       = (const float*)d_in[3];
    const float* W2       = (const float*)d_in[4];
    int nRays = in_sizes[0] / 3;

    transpose_bg<<<(HH * WW + 255) / 256, 256>>>(bg);
    int blocks = (nRays + 255) / 256;
    render_kernel<<<blocks, 256>>>(viewdirs, W1, W2, (float*)d_out, nRays);
}

// round 3
// speedup vs baseline: 1.5440x; 1.5440x over previous
#include <cuda_runtime.h>
#include <cuda_bf16.h>
#include <cstdint>

#define HH 512
#define WW 1024
#define CC 16      // BG_RANK
#define FC 128     // FEATC

// Transposed bf16 background: bgT[y][x][c], 16 bf16 = 32B/texel = 2 uint4. 16 MB.
__device__ uint4 g_bgT[HH * WW * 2];
// Precomputed per-lane mma B-fragments.
// W1: [t=0..15][lane] -> (b0,b1) ; W2: [q=0..7][lane] -> (b0,b1)
__device__ uint2 g_w1f[16 * 32];
__device__ uint2 g_w2f[8 * 32];

static __device__ __forceinline__ uint32_t bits2(__nv_bfloat162 h) {
    return *reinterpret_cast<uint32_t*>(&h);
}

// ---------------------------------------------------------------------------
// Kernel 1: transpose bg_mat [16][512][1024] fp32 -> g_bgT [512*1024][16] bf16
// ---------------------------------------------------------------------------
__global__ void transpose_bg(const float* __restrict__ bg) {
    int idx = blockIdx.x * blockDim.x + threadIdx.x;   // y*WW + x
    if (idx >= HH * WW) return;
    uint32_t p[8];
#pragma unroll
    for (int c = 0; c < 8; c++) {
        float a = bg[(2 * c)     * (HH * WW) + idx];
        float b = bg[(2 * c + 1) * (HH * WW) + idx];
        p[c] = bits2(__floats2bfloat162_rn(a, b));     // lo = ch 2c, hi = ch 2c+1
    }
    g_bgT[idx * 2 + 0] = make_uint4(p[0], p[1], p[2], p[3]);
    g_bgT[idx * 2 + 1] = make_uint4(p[4], p[5], p[6], p[7]);
}

// ---------------------------------------------------------------------------
// Kernel 2: build per-lane B fragments for both GEMMs (m16n8k16.row.col).
// B frag thread(g,tg): b0=(B[2tg][g],B[2tg+1][g]) b1=(B[2tg+8][g],B[2tg+9][g])
// W1 chunk t covers cols t*8+g ; W2 chunk q covers k rows 16q.., col g (<3).
// ---------------------------------------------------------------------------
__global__ void build_frags(const float* __restrict__ W1,
                            const float* __restrict__ W2) {
    int tid  = blockIdx.x * blockDim.x + threadIdx.x;
    int lane = tid & 31;
    int g  = lane >> 2;
    int tg = lane & 3;
    if (tid < 512) {                       // W1 fragments: t = tid>>5
        int t   = tid >> 5;
        int col = t * 8 + g;
        int k0  = 2 * tg;
        uint32_t b0 = bits2(__floats2bfloat162_rn(W1[(k0    ) * FC + col],
                                                  W1[(k0 + 1) * FC + col]));
        uint32_t b1 = bits2(__floats2bfloat162_rn(W1[(k0 + 8) * FC + col],
                                                  W1[(k0 + 9) * FC + col]));
        g_w1f[tid] = make_uint2(b0, b1);
    } else if (tid < 768) {                // W2 fragments: q = (tid-512)>>5
        int q  = (tid - 512) >> 5;
        int k0 = 16 * q + 2 * tg;
        float v00 = (g < 3) ? W2[(k0    ) * 3 + g] : 0.f;
        float v01 = (g < 3) ? W2[(k0 + 1) * 3 + g] : 0.f;
        float v10 = (g < 3) ? W2[(k0 + 8) * 3 + g] : 0.f;
        float v11 = (g < 3) ? W2[(k0 + 9) * 3 + g] : 0.f;
        uint32_t b0 = bits2(__floats2bfloat162_rn(v00, v01));
        uint32_t b1 = bits2(__floats2bfloat162_rn(v10, v11));
        g_w2f[tid - 512] = make_uint2(b0, b1);
    }
}

#define MMA16816(D0, D1, D2, D3, A0, A1, A2, A3, B0, B1)                        \
    asm volatile(                                                               \
        "mma.sync.aligned.m16n8k16.row.col.f32.bf16.bf16.f32 "                  \
        "{%0,%1,%2,%3},{%4,%5,%6,%7},{%8,%9},{%0,%1,%2,%3};"                    \
        : "+f"(D0), "+f"(D1), "+f"(D2), "+f"(D3)                                \
        : "r"(A0), "r"(A1), "r"(A2), "r"(A3), "r"(B0), "r"(B1))

static __device__ __forceinline__ uint32_t packrelu(float a, float b) {
    return bits2(__floats2bfloat162_rn(fmaxf(a, 0.f), fmaxf(b, 0.f)));
}

static __device__ __forceinline__ float softplusf(float x) {
    return fmaxf(x, 0.f) + log1pf(expf(-fabsf(x)));
}

// ---------------------------------------------------------------------------
// Kernel 3: per-warp 32-ray pipeline, fully tensorized MLP.
//   unwrap -> bilinear gather (bf16 texels, fp32 blend) -> stage -> ldmatrix
//   -> loop q=0..7: 4x mma (h chunks 2q,2q+1, both 16-ray tiles)
//                   -> relu+pack (acc IS the next A-fragment)
//                   -> 2x mma vs W2 fragments (out accumulators)
//   -> softplus -> store (tg0: cols 0,1 ; tg1: col 2)
// ---------------------------------------------------------------------------
__global__ void __launch_bounds__(128, 5)
render_kernel(const float* __restrict__ viewdirs,
              float* __restrict__ out,
              int nRays)
{
    __shared__ __align__(16) uint32_t Astage[4 * 384];  // per warp: 32 rows * 48B

    const int tid  = threadIdx.x;
    const int lane = tid & 31;
    const int warp = tid >> 5;
    const int g    = lane >> 2;
    const int tg   = lane & 3;

    const int rayBase = blockIdx.x * 128 + warp * 32;
    const int ray     = rayBase + lane;

    // ---- load per-lane weight fragments (coalesced, L1/L2-resident) ----
    uint2 w1f[16];
#pragma unroll
    for (int t = 0; t < 16; t++) w1f[t] = g_w1f[t * 32 + lane];

    // ---- unwrap + bilinear gather (fp32 blend of bf16 texels) ----
    float emb[16];
#pragma unroll
    for (int c = 0; c < 16; c++) emb[c] = 0.f;

    if (ray < nRays) {
        float dx = viewdirs[3 * ray + 0];
        float dy = viewdirs[3 * ray + 1];
        float dz = viewdirs[3 * ray + 2];
        const float INV_PI = 0.318309886183790671538f;
        float phi   = atan2f(dy, dx);
        float theta = acosf(fminf(fmaxf(dz, -1.f), 1.f));
        float gx = phi * INV_PI;
        float gy = theta * (2.f * INV_PI) - 1.f;
        float ix = (gx + 1.f) * (0.5f * WW) - 0.5f;
        float iy = (gy + 1.f) * (0.5f * HH) - 0.5f;
        float x0 = floorf(ix), y0 = floorf(iy);
        float fx = ix - x0,    fy = iy - y0;
        float wx[2] = {1.f - fx, fx};
        float wy[2] = {1.f - fy, fy};
#pragma unroll
        for (int cy = 0; cy < 2; cy++) {
#pragma unroll
            for (int cx = 0; cx < 2; cx++) {
                float xf = x0 + (float)cx;
                float yf = y0 + (float)cy;
                bool valid = (xf >= 0.f) & (xf <= (float)(WW - 1)) &
                             (yf >= 0.f) & (yf <= (float)(HH - 1));
                float w = wx[cx] * wy[cy] * (valid ? 1.f : 0.f);
                int xi = (int)fminf(fmaxf(xf, 0.f), (float)(WW - 1));
                int yi = (int)fminf(fmaxf(yf, 0.f), (float)(HH - 1));
                const uint4* p = &g_bgT[(yi * WW + xi) * 2];
                uint4 v0 = p[0];
                uint4 v1 = p[1];
                uint32_t u[8] = {v0.x, v0.y, v0.z, v0.w, v1.x, v1.y, v1.z, v1.w};
#pragma unroll
                for (int j = 0; j < 8; j++) {
                    float lo = __uint_as_float(u[j] << 16);          // ch 2j
                    float hi = __uint_as_float(u[j] & 0xffff0000u);  // ch 2j+1
                    emb[2 * j + 0] = fmaf(w, lo, emb[2 * j + 0]);
                    emb[2 * j + 1] = fmaf(w, hi, emb[2 * j + 1]);
                }
            }
        }
    }

    // ---- stage A row (16 bf16 = 32B) at 48B stride (conflict-free) ----
    {
        uint32_t pk[8];
#pragma unroll
        for (int j = 0; j < 8; j++)
            pk[j] = bits2(__floats2bfloat162_rn(emb[2 * j], emb[2 * j + 1]));
        uint4* arow = reinterpret_cast<uint4*>(&Astage[warp * 384 + lane * 12]);
        arow[0] = make_uint4(pk[0], pk[1], pk[2], pk[3]);
        arow[1] = make_uint4(pk[4], pk[5], pk[6], pk[7]);
    }
    __syncwarp();

    // ---- ldmatrix x4: tile0 = rays 0..15, tile1 = rays 16..31 ----
    uint32_t a0[4], a1[4];
    {
        int m = lane >> 3;
        int r = lane & 7;
        int row    = (m & 1) * 8 + r;
        int coloff = (m >> 1) * 16;
        uint32_t base  = (uint32_t)__cvta_generic_to_shared(&Astage[warp * 384]);
        uint32_t addr0 = base + row * 48 + coloff;
        uint32_t addr1 = addr0 + 16 * 48;
        asm volatile("ldmatrix.sync.aligned.m8n8.x4.shared.b16 {%0,%1,%2,%3}, [%4];"
                     : "=r"(a0[0]), "=r"(a0[1]), "=r"(a0[2]), "=r"(a0[3]) : "r"(addr0));
        asm volatile("ldmatrix.sync.aligned.m8n8.x4.shared.b16 {%0,%1,%2,%3}, [%4];"
                     : "=r"(a1[0]), "=r"(a1[1]), "=r"(a1[2]), "=r"(a1[3]) : "r"(addr1));
    }

    // ---- fused MLP: h = emb@W1 (mma) -> relu/pack -> out += h@W2 (mma) ----
    float oa[8];
#pragma unroll
    for (int i = 0; i < 8; i++) oa[i] = 0.f;

#pragma unroll
    for (int q = 0; q < 8; q++) {
        float p0 = 0.f, p1 = 0.f, p2 = 0.f, p3 = 0.f;   // tile0, t=2q
        float p4 = 0.f, p5 = 0.f, p6 = 0.f, p7 = 0.f;   // tile1, t=2q
        float r0 = 0.f, r1 = 0.f, r2 = 0.f, r3 = 0.f;   // tile0, t=2q+1
        float r4 = 0.f, r5 = 0.f, r6 = 0.f, r7 = 0.f;   // tile1, t=2q+1
        uint2 wA = w1f[2 * q];
        uint2 wB = w1f[2 * q + 1];
        MMA16816(p0, p1, p2, p3, a0[0], a0[1], a0[2], a0[3], wA.x, wA.y);
        MMA16816(p4, p5, p6, p7, a1[0], a1[1], a1[2], a1[3], wA.x, wA.y);
        MMA16816(r0, r1, r2, r3, a0[0], a0[1], a0[2], a0[3], wB.x, wB.y);
        MMA16816(r4, r5, r6, r7, a1[0], a1[1], a1[2], a1[3], wB.x, wB.y);

        // acc(m16n8) of chunks (2q, 2q+1) == A-fragment(m16k16) of h chunk q
        uint32_t f00 = packrelu(p0, p1);   // tile0 a0: row g,   k 2tg..
        uint32_t f01 = packrelu(p2, p3);   // tile0 a1: row g+8
        uint32_t f02 = packrelu(r0, r1);   // tile0 a2: row g,   k 8+2tg..
        uint32_t f03 = packrelu(r2, r3);   // tile0 a3: row g+8
        uint32_t f10 = packrelu(p4, p5);
        uint32_t f11 = packrelu(p6, p7);
        uint32_t f12 = packrelu(r4, r5);
        uint32_t f13 = packrelu(r6, r7);

        uint2 w2 = g_w2f[q * 32 + lane];
        MMA16816(oa[0], oa[1], oa[2], oa[3], f00, f01, f02, f03, w2.x, w2.y);
        MMA16816(oa[4], oa[5], oa[6], oa[7], f10, f11, f12, f13, w2.x, w2.y);
    }

    // ---- softplus + store. Out acc cols = 2tg,2tg+1; only cols 0..2 live. ----
    // tile0: rows g (oa0,oa1), g+8 (oa2,oa3); tile1: rows g+16, g+24.
    if (tg == 0) {
#pragma unroll
        for (int k = 0; k < 4; k++) {
            int rr = rayBase + g + 8 * k;
            if (rr < nRays) {
                out[rr * 3 + 0] = softplusf(oa[2 * k + 0]);
                out[rr * 3 + 1] = softplusf(oa[2 * k + 1]);
            }
        }
    } else if (tg == 1) {
#pragma unroll
        for (int k = 0; k < 4; k++) {
            int rr = rayBase + g + 8 * k;
            if (rr < nRays)
                out[rr * 3 + 2] = softplusf(oa[2 * k + 0]);   // col 2
        }
    }
}

// ---------------------------------------------------------------------------
// Launch. Inputs (metadata order): viewdirs, roughness(unused), bg_mat, W1, W2.
// Graph-capturable, allocation-free.
// ---------------------------------------------------------------------------
extern "C" void kernel_launch(void* const* d_in, const int* in_sizes, int n_in,
                              void* d_out, int out_size) {
    const float* viewdirs = (const float*)d_in[0];
    const float* bg       = (const float*)d_in[2];
    const float* W1       = (const float*)d_in[3];
    const float* W2       = (const float*)d_in[4];
    int nRays = in_sizes[0] / 3;

    transpose_bg<<<(HH * WW + 255) / 256, 256>>>(bg);
    build_frags<<<1, 768>>>(W1, W2);
    int blocks = (nRays + 127) / 128;
    render_kernel<<<blocks, 128>>>(viewdirs, (float*)d_out, nRays);
}